// round 4
// baseline (speedup 1.0000x reference)
#include <cuda_runtime.h>

#define BTOT 16384
#define TENC 256
#define NIN 6
#define GROUPS 8
#define RR 14
#define ROWS (GROUPS * RR)          /* 112 rows per block */
#define NTHREADS 512
#define NBLOCKS ((BTOT + ROWS - 1) / ROWS)   /* 147 */

/* ---------------- shared memory layout (float offsets) ---------------- */
#define SZW (3 * 64 * 68)           /* one 192x64 matrix, pitch-68 padded */
#define OFF_WHH0 0
#define OFF_WIH1 (SZW)
#define OFF_WHH1 (2 * SZW)
#define OFF_WIH0 (3 * SZW)          /* enc: [3][6][64]=1152 ; dec: [192]  */
#define OFF_BIH0 (OFF_WIH0 + 1152)
#define OFF_BHH0 (OFF_BIH0 + 192)
#define OFF_BIH1 (OFF_BHH0 + 192)
#define OFF_BHH1 (OFF_BIH1 + 192)
#define OFF_WON  (OFF_BHH1 + 192)
#define OFF_WCV  (OFF_WON + 64)
#define OFF_BON  (OFF_WCV + 64)
#define OFF_BCV  (OFF_BON + 1)
#define OFF_H0   ((OFF_BCV + 1 + 3) & ~3)   /* 16B-aligned for float4 */
#define OFF_H1   (OFF_H0 + ROWS * 64)
#define OFF_XS   (OFF_H1 + ROWS * 64)
#define OFF_PREV (OFF_XS + ROWS * 8)
#define OFF_RED  (OFF_PREV + ROWS)
#define SMEM_FLOATS (OFF_RED + GROUPS * 2 * 2 * RR)
#define SMEM_BYTES (SMEM_FLOATS * 4)

__device__ __forceinline__ float sigf(float x) {
    return __fdividef(1.0f, 1.0f + __expf(-x));
}
__device__ __forceinline__ float tanh_(float x) {
    float xc = fminf(fmaxf(x, -15.0f), 15.0f);
    float e  = __expf(2.0f * xc);
    return __fdividef(e - 1.0f, e + 1.0f);
}

__device__ __forceinline__ float fma4(float acc, float4 a, float4 b) {
    acc = fmaf(a.x, b.x, acc);
    acc = fmaf(a.y, b.y, acc);
    acc = fmaf(a.z, b.z, acc);
    acc = fmaf(a.w, b.w, acc);
    return acc;
}

/* 3-gate matmul over one 192x64 matrix against hidden buffer HB (pitch 64) */
#define MM3(WOFF, HB)                                                          \
    do {                                                                       \
        _Pragma("unroll 2")                                                    \
        for (int kk = 0; kk < 64; kk += 4) {                                   \
            const float4 wr = *(const float4*)&sm[(WOFF) + (j) * 68 + kk];     \
            const float4 wz = *(const float4*)&sm[(WOFF) + (64 + j) * 68 + kk];\
            const float4 wn = *(const float4*)&sm[(WOFF) + (128 + j) * 68 + kk];\
            _Pragma("unroll")                                                  \
            for (int r = 0; r < RR; r++) {                                     \
                const float4 hv = *(const float4*)&(HB)[r * 64 + kk];          \
                ar[r]  = fma4(ar[r],  wr, hv);                                 \
                az[r]  = fma4(az[r],  wz, hv);                                 \
                anh[r] = fma4(anh[r], wn, hv);                                 \
            }                                                                  \
        }                                                                      \
    } while (0)

/* fused layer-1: input matmul (Wih1 @ h0) + hidden matmul (Whh1 @ h1) */
#define MM3FUSED()                                                             \
    do {                                                                       \
        _Pragma("unroll 2")                                                    \
        for (int kk = 0; kk < 64; kk += 4) {                                   \
            const float4 ir = *(const float4*)&sm[OFF_WIH1 + (j) * 68 + kk];   \
            const float4 iz = *(const float4*)&sm[OFF_WIH1 + (64 + j) * 68 + kk];\
            const float4 in_ = *(const float4*)&sm[OFF_WIH1 + (128 + j) * 68 + kk];\
            const float4 hr = *(const float4*)&sm[OFF_WHH1 + (j) * 68 + kk];   \
            const float4 hz = *(const float4*)&sm[OFF_WHH1 + (64 + j) * 68 + kk];\
            const float4 hn = *(const float4*)&sm[OFF_WHH1 + (128 + j) * 68 + kk];\
            _Pragma("unroll")                                                  \
            for (int r = 0; r < RR; r++) {                                     \
                const float4 a4 = *(const float4*)&h0b[r * 64 + kk];           \
                const float4 b4 = *(const float4*)&h1b[r * 64 + kk];           \
                ar[r]  = fma4(ar[r],  ir,  a4);                                \
                ar[r]  = fma4(ar[r],  hr,  b4);                                \
                az[r]  = fma4(az[r],  iz,  a4);                                \
                az[r]  = fma4(az[r],  hz,  b4);                                \
                ani[r] = fma4(ani[r], in_, a4);                                \
                anh[r] = fma4(anh[r], hn,  b4);                                \
            }                                                                  \
        }                                                                      \
    } while (0)

__global__ void __launch_bounds__(NTHREADS, 1)
ccseq_kernel(const float* __restrict__ x,
             const float* __restrict__ eWih0, const float* __restrict__ eWhh0,
             const float* __restrict__ eBih0, const float* __restrict__ eBhh0,
             const float* __restrict__ eWih1, const float* __restrict__ eWhh1,
             const float* __restrict__ eBih1, const float* __restrict__ eBhh1,
             const float* __restrict__ dWih0, const float* __restrict__ dWhh0,
             const float* __restrict__ dBih0, const float* __restrict__ dBhh0,
             const float* __restrict__ dWih1, const float* __restrict__ dWhh1,
             const float* __restrict__ dBih1, const float* __restrict__ dBhh1,
             const float* __restrict__ Won, const float* __restrict__ bOn,
             const float* __restrict__ Wcv, const float* __restrict__ bCv,
             float* __restrict__ out, int L)
{
    extern __shared__ float sm[];
    const int tid  = threadIdx.x;
    const int g    = tid >> 6;
    const int j    = tid & 63;
    const int lane = tid & 31;
    const int w2   = (tid >> 5) & 1;

    /* -------- load encoder weights into SMEM -------- */
    for (int idx = tid; idx < 192 * 64; idx += NTHREADS) {
        int row = idx >> 6, k = idx & 63;
        sm[OFF_WHH0 + row * 68 + k] = eWhh0[idx];
        sm[OFF_WIH1 + row * 68 + k] = eWih1[idx];
        sm[OFF_WHH1 + row * 68 + k] = eWhh1[idx];
    }
    for (int idx = tid; idx < 3 * 6 * 64; idx += NTHREADS) {
        int jj = idx & 63, t2 = idx >> 6;
        int i = t2 % 6, gate = t2 / 6;
        sm[OFF_WIH0 + idx] = eWih0[(gate * 64 + jj) * NIN + i];
    }
    for (int idx = tid; idx < 192; idx += NTHREADS) {
        sm[OFF_BIH0 + idx] = eBih0[idx];
        sm[OFF_BHH0 + idx] = eBhh0[idx];
        sm[OFF_BIH1 + idx] = eBih1[idx];
        sm[OFF_BHH1 + idx] = eBhh1[idx];
    }
    for (int idx = tid; idx < ROWS * 64; idx += NTHREADS) {
        sm[OFF_H0 + idx] = 0.0f;
        sm[OFF_H1 + idx] = 0.0f;
    }
    __syncthreads();

    float b0r = sm[OFF_BIH0 + j] + sm[OFF_BHH0 + j];
    float b0z = sm[OFF_BIH0 + 64 + j] + sm[OFF_BHH0 + 64 + j];
    float b0in = sm[OFF_BIH0 + 128 + j];
    float b0hn = sm[OFF_BHH0 + 128 + j];
    float b1r = sm[OFF_BIH1 + j] + sm[OFF_BHH1 + j];
    float b1z = sm[OFF_BIH1 + 64 + j] + sm[OFF_BHH1 + 64 + j];
    float b1in = sm[OFF_BIH1 + 128 + j];
    float b1hn = sm[OFF_BHH1 + 128 + j];

    float h0[RR], h1[RR];
#pragma unroll
    for (int r = 0; r < RR; r++) { h0[r] = 0.0f; h1[r] = 0.0f; }

    const float* h0b = sm + OFF_H0 + g * RR * 64;
    const float* h1b = sm + OFF_H1 + g * RR * 64;

    /* ======================= encoder ======================= */
    for (int t = 0; t < TENC; t++) {
        for (int idx = tid; idx < ROWS * NIN; idx += NTHREADS) {
            int rl = idx / NIN, i = idx - rl * NIN;
            int row = blockIdx.x * ROWS + rl;
            if (row >= BTOT) row = BTOT - 1;
            sm[OFF_XS + rl * 8 + i] = x[row * (TENC * NIN) + t * NIN + i];
        }
        __syncthreads();

        float ar[RR], az[RR], ani[RR], anh[RR];
#pragma unroll
        for (int r = 0; r < RR; r++) { ar[r] = 0.f; az[r] = 0.f; ani[r] = 0.f; anh[r] = 0.f; }

        MM3(OFF_WHH0, h0b);
#pragma unroll
        for (int i = 0; i < NIN; i++) {
            float wr = sm[OFF_WIH0 + i * 64 + j];
            float wz = sm[OFF_WIH0 + (6 + i) * 64 + j];
            float wn = sm[OFF_WIH0 + (12 + i) * 64 + j];
#pragma unroll
            for (int r = 0; r < RR; r++) {
                float xv = sm[OFF_XS + (g * RR + r) * 8 + i];
                ar[r] = fmaf(wr, xv, ar[r]);
                az[r] = fmaf(wz, xv, az[r]);
                ani[r] = fmaf(wn, xv, ani[r]);
            }
        }
#pragma unroll
        for (int r = 0; r < RR; r++) {
            float rg = sigf(ar[r] + b0r);
            float zg = sigf(az[r] + b0z);
            float ng = tanh_(ani[r] + b0in + rg * (anh[r] + b0hn));
            h0[r] = ng + zg * (h0[r] - ng);
        }
        __syncthreads();
#pragma unroll
        for (int r = 0; r < RR; r++) sm[OFF_H0 + (g * RR + r) * 64 + j] = h0[r];
        __syncthreads();

#pragma unroll
        for (int r = 0; r < RR; r++) { ar[r] = 0.f; az[r] = 0.f; ani[r] = 0.f; anh[r] = 0.f; }
        MM3FUSED();
#pragma unroll
        for (int r = 0; r < RR; r++) {
            float rg = sigf(ar[r] + b1r);
            float zg = sigf(az[r] + b1z);
            float ng = tanh_(ani[r] + b1in + rg * (anh[r] + b1hn));
            h1[r] = ng + zg * (h1[r] - ng);
        }
        __syncthreads();   /* all layer-1 reads of h1s finished */
#pragma unroll
        for (int r = 0; r < RR; r++) sm[OFF_H1 + (g * RR + r) * 64 + j] = h1[r];
        /* visibility covered by first sync of next iteration / phase switch */
    }

    /* -------- swap in decoder weights -------- */
    __syncthreads();
    for (int idx = tid; idx < 192 * 64; idx += NTHREADS) {
        int row = idx >> 6, k = idx & 63;
        sm[OFF_WHH0 + row * 68 + k] = dWhh0[idx];
        sm[OFF_WIH1 + row * 68 + k] = dWih1[idx];
        sm[OFF_WHH1 + row * 68 + k] = dWhh1[idx];
    }
    for (int idx = tid; idx < 192; idx += NTHREADS) {
        sm[OFF_WIH0 + idx] = dWih0[idx];   /* [192][1] */
        sm[OFF_BIH0 + idx] = dBih0[idx];
        sm[OFF_BHH0 + idx] = dBhh0[idx];
        sm[OFF_BIH1 + idx] = dBih1[idx];
        sm[OFF_BHH1 + idx] = dBhh1[idx];
    }
    for (int idx = tid; idx < 64; idx += NTHREADS) {
        sm[OFF_WON + idx] = Won[idx];
        sm[OFF_WCV + idx] = Wcv[idx];
    }
    if (tid == 0) { sm[OFF_BON] = bOn[0]; sm[OFF_BCV] = bCv[0]; }
    for (int idx = tid; idx < ROWS; idx += NTHREADS) sm[OFF_PREV + idx] = 0.0f;
    __syncthreads();

    b0r = sm[OFF_BIH0 + j] + sm[OFF_BHH0 + j];
    b0z = sm[OFF_BIH0 + 64 + j] + sm[OFF_BHH0 + 64 + j];
    b0in = sm[OFF_BIH0 + 128 + j];
    b0hn = sm[OFF_BHH0 + 128 + j];
    b1r = sm[OFF_BIH1 + j] + sm[OFF_BHH1 + j];
    b1z = sm[OFF_BIH1 + 64 + j] + sm[OFF_BHH1 + 64 + j];
    b1in = sm[OFF_BIH1 + 128 + j];
    b1hn = sm[OFF_BHH1 + 128 + j];
    const float w0r = sm[OFF_WIH0 + j];
    const float w0z = sm[OFF_WIH0 + 64 + j];
    const float w0n = sm[OFF_WIH0 + 128 + j];
    const float won_ = sm[OFF_WON + j];
    const float wcv_ = sm[OFF_WCV + j];

    /* ======================= decoder ======================= */
    for (int t = 0; t < L; t++) {
        float ar[RR], az[RR], ani[RR], anh[RR];
#pragma unroll
        for (int r = 0; r < RR; r++) { ar[r] = 0.f; az[r] = 0.f; ani[r] = 0.f; anh[r] = 0.f; }

        MM3(OFF_WHH0, h0b);
#pragma unroll
        for (int r = 0; r < RR; r++) {
            float pv = sm[OFF_PREV + g * RR + r];
            ar[r] = fmaf(w0r, pv, ar[r]);
            az[r] = fmaf(w0z, pv, az[r]);
            ani[r] = fmaf(w0n, pv, ani[r]);
        }
#pragma unroll
        for (int r = 0; r < RR; r++) {
            float rg = sigf(ar[r] + b0r);
            float zg = sigf(az[r] + b0z);
            float ng = tanh_(ani[r] + b0in + rg * (anh[r] + b0hn));
            h0[r] = ng + zg * (h0[r] - ng);
        }
        __syncthreads();
#pragma unroll
        for (int r = 0; r < RR; r++) sm[OFF_H0 + (g * RR + r) * 64 + j] = h0[r];
        __syncthreads();

#pragma unroll
        for (int r = 0; r < RR; r++) { ar[r] = 0.f; az[r] = 0.f; ani[r] = 0.f; anh[r] = 0.f; }
        MM3FUSED();
#pragma unroll
        for (int r = 0; r < RR; r++) {
            float rg = sigf(ar[r] + b1r);
            float zg = sigf(az[r] + b1z);
            float ng = tanh_(ani[r] + b1in + rg * (anh[r] + b1hn));
            h1[r] = ng + zg * (h1[r] - ng);
        }

        /* heads: dot(h1, Won/Wcv) reduced across the 64-thread group */
        float po[RR], pc[RR];
#pragma unroll
        for (int r = 0; r < RR; r++) { po[r] = won_ * h1[r]; pc[r] = wcv_ * h1[r]; }
#pragma unroll
        for (int r = 0; r < RR; r++) {
#pragma unroll
            for (int off = 16; off; off >>= 1) {
                po[r] += __shfl_xor_sync(0xffffffffu, po[r], off);
                pc[r] += __shfl_xor_sync(0xffffffffu, pc[r], off);
            }
        }
        if (lane == 0) {
#pragma unroll
            for (int r = 0; r < RR; r++) {
                sm[OFF_RED + (g * 4 + w2 * 2 + 0) * RR + r] = po[r];
                sm[OFF_RED + (g * 4 + w2 * 2 + 1) * RR + r] = pc[r];
            }
        }
        __syncthreads();   /* red visible; all layer-1 reads of h1s finished */
#pragma unroll
        for (int r = 0; r < RR; r++) sm[OFF_H1 + (g * RR + r) * 64 + j] = h1[r];

        if (j < RR) {
            int r = j;
            float oo = sm[OFF_RED + (g * 4 + 0) * RR + r] +
                       sm[OFF_RED + (g * 4 + 2) * RR + r] + sm[OFF_BON];
            float cc = sm[OFF_RED + (g * 4 + 1) * RR + r] +
                       sm[OFF_RED + (g * 4 + 3) * RR + r] + sm[OFF_BCV];
            float gated = (oo > 0.0f) ? cc : 0.0f;   /* sigmoid(oo) > 0.5 */
            sm[OFF_PREV + g * RR + r] = gated;
            int row = blockIdx.x * ROWS + g * RR + r;
            if (row < BTOT) out[row * L + t] = gated;
        }
        __syncthreads();   /* prev + h1s visible for next step */
    }
}

extern "C" void kernel_launch(void* const* d_in, const int* in_sizes, int n_in,
                              void* d_out, int out_size)
{
    const float* x     = (const float*)d_in[0];
    /* d_in[1] = target_len (device scalar) — derived from out_size instead */
    const float* eWih0 = (const float*)d_in[2];
    const float* eWhh0 = (const float*)d_in[3];
    const float* eBih0 = (const float*)d_in[4];
    const float* eBhh0 = (const float*)d_in[5];
    const float* eWih1 = (const float*)d_in[6];
    const float* eWhh1 = (const float*)d_in[7];
    const float* eBih1 = (const float*)d_in[8];
    const float* eBhh1 = (const float*)d_in[9];
    const float* dWih0 = (const float*)d_in[10];
    const float* dWhh0 = (const float*)d_in[11];
    const float* dBih0 = (const float*)d_in[12];
    const float* dBhh0 = (const float*)d_in[13];
    const float* dWih1 = (const float*)d_in[14];
    const float* dWhh1 = (const float*)d_in[15];
    const float* dBih1 = (const float*)d_in[16];
    const float* dBhh1 = (const float*)d_in[17];
    const float* Won   = (const float*)d_in[18];
    const float* bOn   = (const float*)d_in[19];
    const float* Wcv   = (const float*)d_in[20];
    const float* bCv   = (const float*)d_in[21];

    int L = out_size / BTOT;   /* 180 */

    cudaFuncSetAttribute(ccseq_kernel,
                         cudaFuncAttributeMaxDynamicSharedMemorySize, SMEM_BYTES);

    ccseq_kernel<<<NBLOCKS, NTHREADS, SMEM_BYTES>>>(
        x, eWih0, eWhh0, eBih0, eBhh0, eWih1, eWhh1, eBih1, eBhh1,
        dWih0, dWhh0, dBih0, dBhh0, dWih1, dWhh1, dBih1, dBhh1,
        Won, bOn, Wcv, bCv, (float*)d_out, L);
}